// round 15
// baseline (speedup 1.0000x reference)
#include <cuda_runtime.h>
#include <math.h>

#define NT 512
#define NFEAT 1024
#define NCAT 1536
#define MEMSZ 16384
#define RSQRTNF 0.17677669529663689f

// ---- output layout (float element offsets) ----
#define OUT_MEM    0
#define OUT_TMEM   8388608
#define OUT_FMEM   8404992
#define OUT_ARE    25182208
#define OUT_AIM    25198592
#define OUT_FREQ   25214976
#define OUT_RP     25215008
#define OUT_BIAS   26001440
#define OUT_FMEAN  26001952
#define OUT_AGRE   26002976
#define OUT_AGIM   26019360
#define OUT_FG     26035744
#define OUT_RPG    26035776

// ---- scratch ----
__device__ __align__(16) float g_ux[32 * NFEAT];
__device__ __align__(16) float g_uz[16 * NT];
__device__ __align__(16) float g_G[16 * NT];
__device__ __align__(16) float g_D[16 * NT];
__device__ __align__(16) float g_ct[16 * 32];
__device__ __align__(16) float g_st[16 * 32];
__device__ __align__(16) float g_tp2[32];
__device__ __align__(16) float g_dfr[2][32];
__device__ __align__(16) float g_agre[32 * NT];
__device__ __align__(16) float g_agim[32 * NT];
__device__ __align__(16) float g_fga[2][32];
__device__ __align__(16) float g_rg[NCAT * NT];
__device__ float g_nrm[2][4];
__device__ float g_lr;

__device__ __forceinline__ float sgnf(float v) {
    return (v > 0.f) ? 1.f : ((v < 0.f) ? -1.f : 0.f);
}

__device__ __forceinline__ void trig_one(float fq_f, float cfv, float tt,
                                         float* cv, float* sv, float* dfr) {
    double fq = (double)fq_f;
    double th = tanh(fq);
    double w = (double)cfv + 2.0 * th;
    double sg = 1.0 / (1.0 + exp(-w));
    double ph = (double)tt * (sg * 0.5);
    *cv = (float)cos(ph);
    *sv = (float)sin(ph);
    *dfr = (float)(0.5 * sg * (1.0 - sg) * 2.0 * (1.0 - th * th));
}

// ================= side stream: SM copy with evict-first (streaming) hints =================
__device__ __forceinline__ void copy_one(long long u, int ds,
        const float* __restrict__ memory, const float* __restrict__ fmem,
        const int* __restrict__ tmem, const float* __restrict__ z,
        const float* __restrict__ x, const int* __restrict__ tp,
        float* __restrict__ out) {
    const long long N1 = (long long)MEMSZ * NT / 4;
    const long long N2c = (long long)MEMSZ * NFEAT / 4;
    if (u < N1) {
        int k = (int)u;
        int row = (k * 4) >> 9;
        float4 v;
        if (row == ds) v = *(const float4*)(z + ((k * 4) & 511));
        else           v = __ldcs((const float4*)memory + k);
        __stcs((float4*)(out + OUT_MEM) + k, v);
    } else if (u < N1 + N2c) {
        int k = (int)(u - N1);
        int row = (k * 4) >> 10;
        float4 v;
        if (row == ds) v = *(const float4*)(x + ((k * 4) & 1023));
        else           v = __ldcs((const float4*)fmem + k);
        __stcs((float4*)(out + OUT_FMEM) + k, v);
    } else {
        int k = (int)(u - N1 - N2c);
        int4 iv = __ldcs((const int4*)tmem + k);
        float4 f = make_float4((float)iv.x, (float)iv.y, (float)iv.z, (float)iv.w);
        if ((ds >> 2) == k) ((float*)&f)[ds & 3] = (float)(*tp);
        __stcs((float4*)(out + OUT_TMEM) + k, f);
    }
}

__global__ void k_bigcopy(const float* __restrict__ memory, const float* __restrict__ fmem,
                          const int* __restrict__ tmem,
                          const float* __restrict__ z, const float* __restrict__ x,
                          const int* __restrict__ tp, const int* __restrict__ dsp,
                          float* __restrict__ out) {
    const long long total = (long long)MEMSZ * NT / 4 + (long long)MEMSZ * NFEAT / 4 + MEMSZ / 4;
    long long stride = (long long)gridDim.x * blockDim.x;
    long long u0 = (long long)blockIdx.x * blockDim.x + threadIdx.x;
    int ds = *dsp;
    for (long long u = u0; u < total; u += 4 * stride) {
        copy_one(u, ds, memory, fmem, tmem, z, x, tp, out);
        if (u + stride < total)     copy_one(u + stride, ds, memory, fmem, tmem, z, x, tp, out);
        if (u + 2 * stride < total) copy_one(u + 2 * stride, ds, memory, fmem, tmem, z, x, tp, out);
        if (u + 3 * stride < total) copy_one(u + 3 * stride, ds, memory, fmem, tmem, z, x, tp, out);
    }
}

__global__ void k_misc(const float* __restrict__ bias, const float* __restrict__ fmean,
                       const float* __restrict__ z, const float* __restrict__ x,
                       const int* __restrict__ dsp, float* __restrict__ out) {
    int ds = *dsp;
    float dsn = (float)(ds + 1);
    int u = blockIdx.x * 512 + threadIdx.x;
    if (u < NT) out[OUT_BIAS + u] = (bias[u] * dsn + z[u]) / (dsn + 1.0f);
    if (u < NFEAT) out[OUT_FMEAN + u] = (fmean[u] * dsn + x[u]) / (dsn + 1.0f);
}

// ================= N2: self-gathering eval + r GEMM + G/D  (64 blocks x 256) =================
__global__ void k_N2(int b,
                     const float* __restrict__ freq_p, const float* __restrict__ cf,
                     const float* __restrict__ are_p, const float* __restrict__ aim_p,
                     const float* __restrict__ rp_p,
                     const float* __restrict__ bias_in, const float* __restrict__ z_in,
                     const float* __restrict__ memory, const float* __restrict__ fmem,
                     const int* __restrict__ tmem, const int* __restrict__ ts,
                     const int* __restrict__ tp, const int* __restrict__ dsp,
                     const float* __restrict__ fmean, const float* __restrict__ x) {
    __shared__ float smu[NCAT];
    __shared__ float red[8][32][4];
    __shared__ float sc[32], ss[32];
    int tid = threadIdx.x;
    int i = blockIdx.x >> 2, tq = blockIdx.x & 3;
    int ds = *dsp;
    float dsn = (float)(ds + 1);
    int idx = ts[b * 16 + i];

    if (blockIdx.x == 0) {
        if (tid >= 64 && tid < 68) g_nrm[b][tid - 64] = 0.f;
        if (tid >= 96 && tid < 128) g_fga[b][tid - 96] = 0.f;
        if (tid == 68 && b == 0) g_lr = (float)pow(0.977, (double)(ds + 1));
    }

    // --- pure-input preamble (overlaps the prior update via PDL) ---
    for (int j = tid; j < NFEAT; j += 256) {
        float xv = (idx == ds) ? x[j] : fmem[idx * NFEAT + j];
        float fm = (fmean[j] * dsn + x[j]) / (dsn + 1.0f);
        smu[j] = xv - fm;
        if (tq == 0) g_ux[(b * 16 + i) * NFEAT + j] = xv - fm;
    }
    float tv = (idx == ds) ? (float)(*tp) : (float)tmem[idx];
    float tt = 6.2831853071795864769f * tv;
    if (tq == 0 && tid == 0) g_tp2[b * 16 + i] = tt;

    cudaGridDependencySynchronize();

    if (tid < 32) {
        float cv, sv, dfr;
        trig_one(freq_p[tid], cf[tid], tt, &cv, &sv, &dfr);
        sc[tid] = cv; ss[tid] = sv;
        if (tq == 0) {
            g_ct[i * 32 + tid] = cv;
            g_st[i * 32 + tid] = sv;
        }
        if (blockIdx.x == 0) g_dfr[b][tid] = dfr;
    }
    __syncthreads();

    for (int t2 = tid; t2 < NT; t2 += 256) {
        float acc = 0.f;
#pragma unroll
        for (int f = 0; f < 32; f++)
            acc += sc[f] * are_p[f * NT + t2] - ss[f] * aim_p[f * NT + t2];
        acc *= RSQRTNF;
        smu[NFEAT + t2] = acc;
        if (tq == 0) g_uz[i * NT + t2] = acc;
    }
    __syncthreads();

    {
        int q = tid & 31, js = tid >> 5;
        int tb = tq * 128 + q * 4;
        float a0 = 0.f, a1 = 0.f, a2 = 0.f, a3 = 0.f;
        const float* rpb = rp_p + tb;
        int j0 = js * 192;
#pragma unroll 8
        for (int j = j0; j < j0 + 192; j++) {
            float uv = smu[j];
            float4 rv = *(const float4*)(rpb + (size_t)j * NT);
            a0 += uv * rv.x; a1 += uv * rv.y; a2 += uv * rv.z; a3 += uv * rv.w;
        }
        red[js][q][0] = a0; red[js][q][1] = a1; red[js][q][2] = a2; red[js][q][3] = a3;
    }
    __syncthreads();
    if (tid < 128) {
        int qq = tid >> 2, c = tid & 3;
        float rt = 0.f;
#pragma unroll
        for (int k = 0; k < 8; k++) rt += red[k][qq][c];
        int t = tq * 128 + qq * 4 + c;
        float bv = (bias_in[t] * dsn + z_in[t]) / (dsn + 1.0f);
        float zh = smu[NFEAT + t] + bv;
        float zb = (idx == ds) ? z_in[t] : memory[idx * NT + t];
        float ar = fabsf(rt) + 1.0f;
        float z2 = zh + rt / ar;
        g_G[i * NT + t] = (-0.03f / 16.0f) * sgnf(zb - z2) / (ar * ar);
        g_D[i * NT + t] = (-1.0f / 16.0f) * sgnf(zb - zh);
    }
}

// ===== N3: backD+ampgrad 2t/block (0..255) | rg 8j/block (256..447), 512 thr =====
// PDL: srz (rp z-half rows) and amp rows are stable during N3 (written two+ nodes back)
// => load BEFORE the grid-dependency sync to overlap N2's drain.
__global__ void k_N3(int b, const float* __restrict__ rp_p,
                     const float* __restrict__ are_p, const float* __restrict__ aim_p) {
    if (blockIdx.x < 256) {
        __shared__ float srz[2][NT];
        __shared__ float sD[2][16];
        __shared__ float stt[16];
        int t0 = blockIdx.x * 2, tid = threadIdx.x;
        // --- pre-sync: stable params ---
        srz[0][tid] = rp_p[(size_t)(NFEAT + t0) * NT + tid];
        srz[1][tid] = rp_p[(size_t)(NFEAT + t0 + 1) * NT + tid];
        float are0 = 0.f, aim0 = 0.f;
        if (tid < 64) {
            int tsel = tid >> 5, f = tid & 31;
            are0 = are_p[f * NT + t0 + tsel];
            aim0 = aim_p[f * NT + t0 + tsel];
        }
        cudaGridDependencySynchronize();
        if (tid < 16) stt[tid] = g_tp2[b * 16 + tid];
        __syncthreads();
        int lane = tid & 31, w = tid >> 5;
        float acc0 = 0.f, acc1 = 0.f;
#pragma unroll 4
        for (int tp = lane; tp < NT; tp += 32) {
            float g = g_G[w * NT + tp];
            acc0 += g * srz[0][tp];
            acc1 += g * srz[1][tp];
        }
#pragma unroll
        for (int o = 16; o > 0; o >>= 1) {
            acc0 += __shfl_down_sync(0xffffffffu, acc0, o);
            acc1 += __shfl_down_sync(0xffffffffu, acc1, o);
        }
        if (lane == 0) {
            sD[0][w] = g_D[w * NT + t0] + acc0;
            sD[1][w] = g_D[w * NT + t0 + 1] + acc1;
        }
        __syncthreads();
        if (tid < 64) {
            int tsel = tid >> 5, f = tid & 31;
            int t = t0 + tsel;
            float are = are0, aim = aim0;
            float sre = 0.f, sim = 0.f, sf = 0.f;
#pragma unroll
            for (int i = 0; i < 16; i++) {
                float d = sD[tsel][i];
                float c = g_ct[i * 32 + f];
                float s = g_st[i * 32 + f];
                sre += d * c;
                sim -= d * s;
                sf += d * (-s * are - c * aim) * stt[i];
            }
            float aa = sqrtf(are * are + aim * aim);
            float reg = 0.01f / (2.0f * aa * sqrtf(aa));
            float agre = sre * RSQRTNF + are * reg;
            float agim = sim * RSQRTNF + aim * reg;
            g_agre[f * NT + t] = agre;
            g_agim[f * NT + t] = agim;
            atomicAdd(&g_fga[b][f], sf);
            float nrm = agre * agre + agim * agim;
#pragma unroll
            for (int o = 16; o > 0; o >>= 1)
                nrm += __shfl_down_sync(0xffffffffu, nrm, o);
            if (f == 0) atomicAdd(&g_nrm[b][0], nrm);
        }
    } else {
        __shared__ float su[16][8];
        __shared__ float swr[16];
        int j0 = (blockIdx.x - 256) * 8, tid = threadIdx.x;
        cudaGridDependencySynchronize();
        if (tid < 128) {
            int i = tid >> 3, jj = tid & 7;
            int j = j0 + jj;
            float v = (j < NFEAT) ? g_ux[(b * 16 + i) * NFEAT + j]
                                  : g_uz[i * NT + (j - NFEAT)];
            su[i][jj] = v;
        }
        __syncthreads();
        float a[8] = {0.f, 0.f, 0.f, 0.f, 0.f, 0.f, 0.f, 0.f};
#pragma unroll
        for (int i = 0; i < 16; i++) {
            float gv = g_G[i * NT + tid];
#pragma unroll
            for (int jj = 0; jj < 8; jj++) a[jj] += su[i][jj] * gv;
        }
        float loc = 0.f;
#pragma unroll
        for (int jj = 0; jj < 8; jj++) {
            g_rg[(j0 + jj) * NT + tid] = a[jj];
            loc += a[jj] * a[jj];
        }
#pragma unroll
        for (int o = 16; o > 0; o >>= 1)
            loc += __shfl_down_sync(0xffffffffu, loc, o);
        if ((tid & 31) == 0) swr[tid >> 5] = loc;
        __syncthreads();
        if (tid < 16) {
            loc = swr[tid];
#pragma unroll
            for (int o = 8; o > 0; o >>= 1)
                loc += __shfl_down_sync(0x0000ffffu, loc, o);
            if (tid == 0) atomicAdd(&g_nrm[b][2], loc);
        }
    }
}

// ================= update: momentum + SGD, src -> out =================
// PDL: momentum & param sources are written by the PREVIOUS update (or inputs),
// never by N3 => load before the sync to overlap N3's drain.
__global__ void k_update(int b,
                         const float* __restrict__ rpg_s, const float* __restrict__ rp_s,
                         const float* __restrict__ agre_s, const float* __restrict__ are_s,
                         const float* __restrict__ agim_s, const float* __restrict__ aim_s,
                         const float* __restrict__ fg_s, const float* __restrict__ freq_s,
                         float* __restrict__ out) {
    const int NRP4 = NCAT * NT / 4;
    const int NAMP4 = 32 * NT / 4;
    int idx = blockIdx.x * 256 + threadIdx.x;
    if (idx < NRP4) {
        // pre-sync loads of stable sources
        float4 mo = ((const float4*)rpg_s)[idx];
        float4 pv = ((const float4*)rp_s)[idx];
        cudaGridDependencySynchronize();
        float lr = g_lr;
        float rn = sqrtf(g_nrm[b][2]) + 1.0f;
        float4 gr = ((const float4*)g_rg)[idx];
        mo.x = mo.x * 0.85f + gr.x / rn;  pv.x -= mo.x * lr;
        mo.y = mo.y * 0.85f + gr.y / rn;  pv.y -= mo.y * lr;
        mo.z = mo.z * 0.85f + gr.z / rn;  pv.z -= mo.z * lr;
        mo.w = mo.w * 0.85f + gr.w / rn;  pv.w -= mo.w * lr;
        ((float4*)(out + OUT_RPG))[idx] = mo;
        ((float4*)(out + OUT_RP))[idx] = pv;
    } else if (idx < NRP4 + NAMP4) {
        int k = idx - NRP4;
        float4 mo = ((const float4*)agre_s)[k];
        float4 pv = ((const float4*)are_s)[k];
        float4 mi = ((const float4*)agim_s)[k];
        float4 pi = ((const float4*)aim_s)[k];
        cudaGridDependencySynchronize();
        float lr = g_lr;
        float an = sqrtf(g_nrm[b][0]) + 1.0f;
        float4 gr = ((const float4*)g_agre)[k];
        float4 gi = ((const float4*)g_agim)[k];
        mo.x = mo.x * 0.85f + gr.x / an;  pv.x -= mo.x * lr;
        mo.y = mo.y * 0.85f + gr.y / an;  pv.y -= mo.y * lr;
        mo.z = mo.z * 0.85f + gr.z / an;  pv.z -= mo.z * lr;
        mo.w = mo.w * 0.85f + gr.w / an;  pv.w -= mo.w * lr;
        ((float4*)(out + OUT_AGRE))[k] = mo;
        ((float4*)(out + OUT_ARE))[k] = pv;
        mi.x = mi.x * 0.85f + gi.x / an;  pi.x -= mi.x * lr;
        mi.y = mi.y * 0.85f + gi.y / an;  pi.y -= mi.y * lr;
        mi.z = mi.z * 0.85f + gi.z / an;  pi.z -= mi.z * lr;
        mi.w = mi.w * 0.85f + gi.w / an;  pi.w -= mi.w * lr;
        ((float4*)(out + OUT_AGIM))[k] = mi;
        ((float4*)(out + OUT_AIM))[k] = pi;
    } else {
        cudaGridDependencySynchronize();
    }
    if (blockIdx.x == 0 && threadIdx.x < 32) {
        int f = threadIdx.x;
        float lr = g_lr;
        float fgv = (g_fga[b][f] * RSQRTNF) * g_dfr[b][f];
        float n = fgv * fgv;
#pragma unroll
        for (int o = 16; o > 0; o >>= 1)
            n += __shfl_xor_sync(0xffffffffu, n, o);
        float fn = sqrtf(n) + 1.0f;
        float m = fg_s[f] * 0.85f + fgv / fn;
        out[OUT_FG + f] = m;
        out[OUT_FREQ + f] = freq_s[f] - m * lr;
    }
}

// host-side PDL launch helper
template <typename F, typename... Args>
static inline void pdl(F kfn, dim3 grid, dim3 block, Args... args) {
    cudaLaunchConfig_t cfg = {};
    cfg.gridDim = grid;
    cfg.blockDim = block;
    cfg.stream = 0;
    cudaLaunchAttribute at[1];
    at[0].id = cudaLaunchAttributeProgrammaticStreamSerialization;
    at[0].val.programmaticStreamSerializationAllowed = 1;
    cfg.attrs = at;
    cfg.numAttrs = 1;
    cudaLaunchKernelEx(&cfg, kfn, args...);
}

extern "C" void kernel_launch(void* const* d_in, const int* in_sizes, int n_in,
                              void* d_out, int out_size) {
    const int*   t_p    = (const int*)d_in[0];
    const int*   ds_p   = (const int*)d_in[1];
    const int*   ts     = (const int*)d_in[2];
    const float* x      = (const float*)d_in[3];
    const float* z      = (const float*)d_in[4];
    const float* memory = (const float*)d_in[5];
    const int*   tmem   = (const int*)d_in[6];
    const float* fmem   = (const float*)d_in[7];
    const float* amp_re = (const float*)d_in[8];
    const float* amp_im = (const float*)d_in[9];
    const float* freq   = (const float*)d_in[10];
    const float* cfreq  = (const float*)d_in[11];
    const float* rp     = (const float*)d_in[12];
    const float* fmean  = (const float*)d_in[13];
    const float* bias   = (const float*)d_in[14];
    const float* agre   = (const float*)d_in[15];
    const float* agim   = (const float*)d_in[16];
    const float* fg     = (const float*)d_in[17];
    const float* rpg    = (const float*)d_in[18];
    float* out = (float*)d_out;

    static cudaStream_t s1 = 0;
    static cudaEvent_t e0 = 0, e1 = 0;
    if (!s1) {
        cudaStreamCreateWithFlags(&s1, cudaStreamNonBlocking);
        cudaEventCreateWithFlags(&e0, cudaEventDisableTiming);
        cudaEventCreateWithFlags(&e1, cudaEventDisableTiming);
    }

    const int UPD_BLOCKS = (NCAT * NT / 4 + 32 * NT / 4) / 256;

    cudaEventRecord(e0, 0);

    k_N2<<<64, 256>>>(0, freq, cfreq, amp_re, amp_im, rp, bias, z,
                      memory, fmem, tmem, ts, t_p, ds_p, fmean, x);

    cudaStreamWaitEvent(s1, e0, 0);
    k_misc<<<2, 512, 0, s1>>>(bias, fmean, z, x, ds_p, out);
    k_bigcopy<<<296, 256, 0, s1>>>(memory, fmem, tmem, z, x, t_p, ds_p, out);
    cudaEventRecord(e1, s1);

    // ---- rest of the chain: PDL edges ----
    pdl(k_N3, dim3(448), dim3(512), 0, (const float*)rp,
        (const float*)amp_re, (const float*)amp_im);
    pdl(k_update, dim3(UPD_BLOCKS), dim3(256), 0,
        (const float*)rpg, (const float*)rp, (const float*)agre, (const float*)amp_re,
        (const float*)agim, (const float*)amp_im, (const float*)fg, (const float*)freq, out);
    pdl(k_N2, dim3(64), dim3(256), 1,
        (const float*)(out + OUT_FREQ), (const float*)cfreq,
        (const float*)(out + OUT_ARE), (const float*)(out + OUT_AIM),
        (const float*)(out + OUT_RP), (const float*)bias, (const float*)z,
        (const float*)memory, (const float*)fmem, (const int*)tmem, (const int*)ts,
        (const int*)t_p, (const int*)ds_p, (const float*)fmean, (const float*)x);
    pdl(k_N3, dim3(448), dim3(512), 1, (const float*)(out + OUT_RP),
        (const float*)(out + OUT_ARE), (const float*)(out + OUT_AIM));
    pdl(k_update, dim3(UPD_BLOCKS), dim3(256), 1,
        (const float*)(out + OUT_RPG), (const float*)(out + OUT_RP),
        (const float*)(out + OUT_AGRE), (const float*)(out + OUT_ARE),
        (const float*)(out + OUT_AGIM), (const float*)(out + OUT_AIM),
        (const float*)(out + OUT_FG), (const float*)(out + OUT_FREQ), out);

    // ---- join ----
    cudaStreamWaitEvent(0, e1, 0);
    (void)in_sizes; (void)n_in; (void)out_size;
}

// round 16
// speedup vs baseline: 1.1553x; 1.1553x over previous
#include <cuda_runtime.h>
#include <math.h>

#define NT 512
#define NFEAT 1024
#define NCAT 1536
#define MEMSZ 16384
#define RSQRTNF 0.17677669529663689f

// ---- output layout (float element offsets) ----
#define OUT_MEM    0
#define OUT_TMEM   8388608
#define OUT_FMEM   8404992
#define OUT_ARE    25182208
#define OUT_AIM    25198592
#define OUT_FREQ   25214976
#define OUT_RP     25215008
#define OUT_BIAS   26001440
#define OUT_FMEAN  26001952
#define OUT_AGRE   26002976
#define OUT_AGIM   26019360
#define OUT_FG     26035744
#define OUT_RPG    26035776

// ---- scratch ----
__device__ __align__(16) float g_ux[32 * NFEAT];
__device__ __align__(16) float g_uz[16 * NT];
__device__ __align__(16) float g_G[16 * NT];
__device__ __align__(16) float g_D[16 * NT];
__device__ __align__(16) float g_ct[16 * 32];
__device__ __align__(16) float g_st[16 * 32];
__device__ __align__(16) float g_tp2[32];
__device__ __align__(16) float g_dfr[2][32];
__device__ __align__(16) float g_agre[32 * NT];
__device__ __align__(16) float g_agim[32 * NT];
__device__ __align__(16) float g_fga[2][32];
__device__ __align__(16) float g_rg[NCAT * NT];
__device__ float g_nrm[2][4];
__device__ float g_lr;

__device__ __forceinline__ float sgnf(float v) {
    return (v > 0.f) ? 1.f : ((v < 0.f) ? -1.f : 0.f);
}

__device__ __forceinline__ void trig_one(float fq_f, float cfv, float tt,
                                         float* cv, float* sv, float* dfr) {
    double fq = (double)fq_f;
    double th = tanh(fq);
    double w = (double)cfv + 2.0 * th;
    double sg = 1.0 / (1.0 + exp(-w));
    double ph = (double)tt * (sg * 0.5);
    *cv = (float)cos(ph);
    *sv = (float)sin(ph);
    *dfr = (float)(0.5 * sg * (1.0 - sg) * 2.0 * (1.0 - th * th));
}

// ================= side stream: SM copy with evict-first (streaming) hints =================
__device__ __forceinline__ void copy_one(long long u, int ds,
        const float* __restrict__ memory, const float* __restrict__ fmem,
        const int* __restrict__ tmem, const float* __restrict__ z,
        const float* __restrict__ x, const int* __restrict__ tp,
        float* __restrict__ out) {
    const long long N1 = (long long)MEMSZ * NT / 4;
    const long long N2c = (long long)MEMSZ * NFEAT / 4;
    if (u < N1) {
        int k = (int)u;
        int row = (k * 4) >> 9;
        float4 v;
        if (row == ds) v = *(const float4*)(z + ((k * 4) & 511));
        else           v = __ldcs((const float4*)memory + k);
        __stcs((float4*)(out + OUT_MEM) + k, v);
    } else if (u < N1 + N2c) {
        int k = (int)(u - N1);
        int row = (k * 4) >> 10;
        float4 v;
        if (row == ds) v = *(const float4*)(x + ((k * 4) & 1023));
        else           v = __ldcs((const float4*)fmem + k);
        __stcs((float4*)(out + OUT_FMEM) + k, v);
    } else {
        int k = (int)(u - N1 - N2c);
        int4 iv = __ldcs((const int4*)tmem + k);
        float4 f = make_float4((float)iv.x, (float)iv.y, (float)iv.z, (float)iv.w);
        if ((ds >> 2) == k) ((float*)&f)[ds & 3] = (float)(*tp);
        __stcs((float4*)(out + OUT_TMEM) + k, f);
    }
}

__global__ void k_bigcopy(const float* __restrict__ memory, const float* __restrict__ fmem,
                          const int* __restrict__ tmem,
                          const float* __restrict__ z, const float* __restrict__ x,
                          const int* __restrict__ tp, const int* __restrict__ dsp,
                          float* __restrict__ out) {
    const long long total = (long long)MEMSZ * NT / 4 + (long long)MEMSZ * NFEAT / 4 + MEMSZ / 4;
    long long stride = (long long)gridDim.x * blockDim.x;
    long long u0 = (long long)blockIdx.x * blockDim.x + threadIdx.x;
    int ds = *dsp;
    for (long long u = u0; u < total; u += 4 * stride) {
        copy_one(u, ds, memory, fmem, tmem, z, x, tp, out);
        if (u + stride < total)     copy_one(u + stride, ds, memory, fmem, tmem, z, x, tp, out);
        if (u + 2 * stride < total) copy_one(u + 2 * stride, ds, memory, fmem, tmem, z, x, tp, out);
        if (u + 3 * stride < total) copy_one(u + 3 * stride, ds, memory, fmem, tmem, z, x, tp, out);
    }
}

__global__ void k_misc(const float* __restrict__ bias, const float* __restrict__ fmean,
                       const float* __restrict__ z, const float* __restrict__ x,
                       const int* __restrict__ dsp, float* __restrict__ out) {
    int ds = *dsp;
    float dsn = (float)(ds + 1);
    int u = blockIdx.x * 512 + threadIdx.x;
    if (u < NT) out[OUT_BIAS + u] = (bias[u] * dsn + z[u]) / (dsn + 1.0f);
    if (u < NFEAT) out[OUT_FMEAN + u] = (fmean[u] * dsn + x[u]) / (dsn + 1.0f);
}

// ================= N2: self-gathering eval + r GEMM + G/D  (64 blocks x 256) =================
__global__ void k_N2(int b,
                     const float* __restrict__ freq_p, const float* __restrict__ cf,
                     const float* __restrict__ are_p, const float* __restrict__ aim_p,
                     const float* __restrict__ rp_p,
                     const float* __restrict__ bias_in, const float* __restrict__ z_in,
                     const float* __restrict__ memory, const float* __restrict__ fmem,
                     const int* __restrict__ tmem, const int* __restrict__ ts,
                     const int* __restrict__ tp, const int* __restrict__ dsp,
                     const float* __restrict__ fmean, const float* __restrict__ x) {
    __shared__ float smu[NCAT];
    __shared__ float red[8][32][4];
    __shared__ float sc[32], ss[32];
    int tid = threadIdx.x;
    int i = blockIdx.x >> 2, tq = blockIdx.x & 3;
    int ds = *dsp;
    float dsn = (float)(ds + 1);
    int idx = ts[b * 16 + i];

    if (blockIdx.x == 0) {
        if (tid >= 64 && tid < 68) g_nrm[b][tid - 64] = 0.f;
        if (tid >= 96 && tid < 128) g_fga[b][tid - 96] = 0.f;
        if (tid == 68 && b == 0) g_lr = (float)pow(0.977, (double)(ds + 1));
    }

    // --- pure-input preamble (overlaps the prior update via PDL) ---
    for (int j = tid; j < NFEAT; j += 256) {
        float xv = (idx == ds) ? x[j] : fmem[idx * NFEAT + j];
        float fm = (fmean[j] * dsn + x[j]) / (dsn + 1.0f);
        smu[j] = xv - fm;
        if (tq == 0) g_ux[(b * 16 + i) * NFEAT + j] = xv - fm;
    }
    float tv = (idx == ds) ? (float)(*tp) : (float)tmem[idx];
    float tt = 6.2831853071795864769f * tv;
    if (tq == 0 && tid == 0) g_tp2[b * 16 + i] = tt;

    cudaGridDependencySynchronize();

    if (tid < 32) {
        float cv, sv, dfr;
        trig_one(freq_p[tid], cf[tid], tt, &cv, &sv, &dfr);
        sc[tid] = cv; ss[tid] = sv;
        if (tq == 0) {
            g_ct[i * 32 + tid] = cv;
            g_st[i * 32 + tid] = sv;
        }
        if (blockIdx.x == 0) g_dfr[b][tid] = dfr;
    }
    __syncthreads();

    for (int t2 = tid; t2 < NT; t2 += 256) {
        float acc = 0.f;
#pragma unroll
        for (int f = 0; f < 32; f++)
            acc += sc[f] * are_p[f * NT + t2] - ss[f] * aim_p[f * NT + t2];
        acc *= RSQRTNF;
        smu[NFEAT + t2] = acc;
        if (tq == 0) g_uz[i * NT + t2] = acc;
    }
    __syncthreads();

    {
        int q = tid & 31, js = tid >> 5;
        int tb = tq * 128 + q * 4;
        float a0 = 0.f, a1 = 0.f, a2 = 0.f, a3 = 0.f;
        const float* rpb = rp_p + tb;
        int j0 = js * 192;
#pragma unroll 8
        for (int j = j0; j < j0 + 192; j++) {
            float uv = smu[j];
            float4 rv = *(const float4*)(rpb + (size_t)j * NT);
            a0 += uv * rv.x; a1 += uv * rv.y; a2 += uv * rv.z; a3 += uv * rv.w;
        }
        red[js][q][0] = a0; red[js][q][1] = a1; red[js][q][2] = a2; red[js][q][3] = a3;
    }
    __syncthreads();
    if (tid < 128) {
        int qq = tid >> 2, c = tid & 3;
        float rt = 0.f;
#pragma unroll
        for (int k = 0; k < 8; k++) rt += red[k][qq][c];
        int t = tq * 128 + qq * 4 + c;
        float bv = (bias_in[t] * dsn + z_in[t]) / (dsn + 1.0f);
        float zh = smu[NFEAT + t] + bv;
        float zb = (idx == ds) ? z_in[t] : memory[idx * NT + t];
        float ar = fabsf(rt) + 1.0f;
        float z2 = zh + rt / ar;
        g_G[i * NT + t] = (-0.03f / 16.0f) * sgnf(zb - z2) / (ar * ar);
        g_D[i * NT + t] = (-1.0f / 16.0f) * sgnf(zb - zh);
    }
}

// ===== N3: backD+ampgrad 2t/block (0..255) | rg 8j/block (256..447), 512 thr =====
__global__ void k_N3(int b, const float* __restrict__ rp_p,
                     const float* __restrict__ are_p, const float* __restrict__ aim_p) {
    cudaGridDependencySynchronize();
    if (blockIdx.x < 256) {
        __shared__ float srz[2][NT];
        __shared__ float sD[2][16];
        __shared__ float stt[16];
        int t0 = blockIdx.x * 2, tid = threadIdx.x;
        srz[0][tid] = rp_p[(size_t)(NFEAT + t0) * NT + tid];
        srz[1][tid] = rp_p[(size_t)(NFEAT + t0 + 1) * NT + tid];
        if (tid < 16) stt[tid] = g_tp2[b * 16 + tid];
        __syncthreads();
        int lane = tid & 31, w = tid >> 5;
        float acc0 = 0.f, acc1 = 0.f;
#pragma unroll 4
        for (int tp = lane; tp < NT; tp += 32) {
            float g = g_G[w * NT + tp];
            acc0 += g * srz[0][tp];
            acc1 += g * srz[1][tp];
        }
#pragma unroll
        for (int o = 16; o > 0; o >>= 1) {
            acc0 += __shfl_down_sync(0xffffffffu, acc0, o);
            acc1 += __shfl_down_sync(0xffffffffu, acc1, o);
        }
        if (lane == 0) {
            sD[0][w] = g_D[w * NT + t0] + acc0;
            sD[1][w] = g_D[w * NT + t0 + 1] + acc1;
        }
        __syncthreads();
        if (tid < 64) {
            int tsel = tid >> 5, f = tid & 31;
            int t = t0 + tsel;
            float are = are_p[f * NT + t], aim = aim_p[f * NT + t];
            float sre = 0.f, sim = 0.f, sf = 0.f;
#pragma unroll
            for (int i = 0; i < 16; i++) {
                float d = sD[tsel][i];
                float c = g_ct[i * 32 + f];
                float s = g_st[i * 32 + f];
                sre += d * c;
                sim -= d * s;
                sf += d * (-s * are - c * aim) * stt[i];
            }
            float aa = sqrtf(are * are + aim * aim);
            float reg = 0.01f / (2.0f * aa * sqrtf(aa));
            float agre = sre * RSQRTNF + are * reg;
            float agim = sim * RSQRTNF + aim * reg;
            g_agre[f * NT + t] = agre;
            g_agim[f * NT + t] = agim;
            atomicAdd(&g_fga[b][f], sf);
            float nrm = agre * agre + agim * agim;
#pragma unroll
            for (int o = 16; o > 0; o >>= 1)
                nrm += __shfl_down_sync(0xffffffffu, nrm, o);
            if (f == 0) atomicAdd(&g_nrm[b][0], nrm);
        }
    } else {
        __shared__ float su[16][8];
        __shared__ float swr[16];
        int j0 = (blockIdx.x - 256) * 8, tid = threadIdx.x;
        if (tid < 128) {
            int i = tid >> 3, jj = tid & 7;
            int j = j0 + jj;
            float v = (j < NFEAT) ? g_ux[(b * 16 + i) * NFEAT + j]
                                  : g_uz[i * NT + (j - NFEAT)];
            su[i][jj] = v;
        }
        __syncthreads();
        float a[8] = {0.f, 0.f, 0.f, 0.f, 0.f, 0.f, 0.f, 0.f};
#pragma unroll
        for (int i = 0; i < 16; i++) {
            float gv = g_G[i * NT + tid];
#pragma unroll
            for (int jj = 0; jj < 8; jj++) a[jj] += su[i][jj] * gv;
        }
        float loc = 0.f;
#pragma unroll
        for (int jj = 0; jj < 8; jj++) {
            g_rg[(j0 + jj) * NT + tid] = a[jj];
            loc += a[jj] * a[jj];
        }
#pragma unroll
        for (int o = 16; o > 0; o >>= 1)
            loc += __shfl_down_sync(0xffffffffu, loc, o);
        if ((tid & 31) == 0) swr[tid >> 5] = loc;
        __syncthreads();
        if (tid < 16) {
            loc = swr[tid];
#pragma unroll
            for (int o = 8; o > 0; o >>= 1)
                loc += __shfl_down_sync(0x0000ffffu, loc, o);
            if (tid == 0) atomicAdd(&g_nrm[b][2], loc);
        }
    }
}

// ================= update: momentum + SGD, src -> out =================
__global__ void k_update(int b,
                         const float* __restrict__ rpg_s, const float* __restrict__ rp_s,
                         const float* __restrict__ agre_s, const float* __restrict__ are_s,
                         const float* __restrict__ agim_s, const float* __restrict__ aim_s,
                         const float* __restrict__ fg_s, const float* __restrict__ freq_s,
                         float* __restrict__ out) {
    cudaGridDependencySynchronize();
    const int NRP4 = NCAT * NT / 4;
    const int NAMP4 = 32 * NT / 4;
    int idx = blockIdx.x * 256 + threadIdx.x;
    float lr = g_lr;
    if (idx < NRP4) {
        float rn = sqrtf(g_nrm[b][2]) + 1.0f;
        float4 mo = ((const float4*)rpg_s)[idx];
        float4 gr = ((const float4*)g_rg)[idx];
        float4 pv = ((const float4*)rp_s)[idx];
        mo.x = mo.x * 0.85f + gr.x / rn;  pv.x -= mo.x * lr;
        mo.y = mo.y * 0.85f + gr.y / rn;  pv.y -= mo.y * lr;
        mo.z = mo.z * 0.85f + gr.z / rn;  pv.z -= mo.z * lr;
        mo.w = mo.w * 0.85f + gr.w / rn;  pv.w -= mo.w * lr;
        ((float4*)(out + OUT_RPG))[idx] = mo;
        ((float4*)(out + OUT_RP))[idx] = pv;
    } else if (idx < NRP4 + NAMP4) {
        int k = idx - NRP4;
        float an = sqrtf(g_nrm[b][0]) + 1.0f;
        float4 mo = ((const float4*)agre_s)[k];
        float4 gr = ((const float4*)g_agre)[k];
        float4 pv = ((const float4*)are_s)[k];
        mo.x = mo.x * 0.85f + gr.x / an;  pv.x -= mo.x * lr;
        mo.y = mo.y * 0.85f + gr.y / an;  pv.y -= mo.y * lr;
        mo.z = mo.z * 0.85f + gr.z / an;  pv.z -= mo.z * lr;
        mo.w = mo.w * 0.85f + gr.w / an;  pv.w -= mo.w * lr;
        ((float4*)(out + OUT_AGRE))[k] = mo;
        ((float4*)(out + OUT_ARE))[k] = pv;
        float4 mi = ((const float4*)agim_s)[k];
        float4 gi = ((const float4*)g_agim)[k];
        float4 pi = ((const float4*)aim_s)[k];
        mi.x = mi.x * 0.85f + gi.x / an;  pi.x -= mi.x * lr;
        mi.y = mi.y * 0.85f + gi.y / an;  pi.y -= mi.y * lr;
        mi.z = mi.z * 0.85f + gi.z / an;  pi.z -= mi.z * lr;
        mi.w = mi.w * 0.85f + gi.w / an;  pi.w -= mi.w * lr;
        ((float4*)(out + OUT_AGIM))[k] = mi;
        ((float4*)(out + OUT_AIM))[k] = pi;
    }
    if (blockIdx.x == 0 && threadIdx.x < 32) {
        int f = threadIdx.x;
        float fgv = (g_fga[b][f] * RSQRTNF) * g_dfr[b][f];
        float n = fgv * fgv;
#pragma unroll
        for (int o = 16; o > 0; o >>= 1)
            n += __shfl_xor_sync(0xffffffffu, n, o);
        float fn = sqrtf(n) + 1.0f;
        float m = fg_s[f] * 0.85f + fgv / fn;
        out[OUT_FG + f] = m;
        out[OUT_FREQ + f] = freq_s[f] - m * lr;
    }
}

// host-side PDL launch helper
template <typename F, typename... Args>
static inline void pdl(F kfn, dim3 grid, dim3 block, Args... args) {
    cudaLaunchConfig_t cfg = {};
    cfg.gridDim = grid;
    cfg.blockDim = block;
    cfg.stream = 0;
    cudaLaunchAttribute at[1];
    at[0].id = cudaLaunchAttributeProgrammaticStreamSerialization;
    at[0].val.programmaticStreamSerializationAllowed = 1;
    cfg.attrs = at;
    cfg.numAttrs = 1;
    cudaLaunchKernelEx(&cfg, kfn, args...);
}

extern "C" void kernel_launch(void* const* d_in, const int* in_sizes, int n_in,
                              void* d_out, int out_size) {
    const int*   t_p    = (const int*)d_in[0];
    const int*   ds_p   = (const int*)d_in[1];
    const int*   ts     = (const int*)d_in[2];
    const float* x      = (const float*)d_in[3];
    const float* z      = (const float*)d_in[4];
    const float* memory = (const float*)d_in[5];
    const int*   tmem   = (const int*)d_in[6];
    const float* fmem   = (const float*)d_in[7];
    const float* amp_re = (const float*)d_in[8];
    const float* amp_im = (const float*)d_in[9];
    const float* freq   = (const float*)d_in[10];
    const float* cfreq  = (const float*)d_in[11];
    const float* rp     = (const float*)d_in[12];
    const float* fmean  = (const float*)d_in[13];
    const float* bias   = (const float*)d_in[14];
    const float* agre   = (const float*)d_in[15];
    const float* agim   = (const float*)d_in[16];
    const float* fg     = (const float*)d_in[17];
    const float* rpg    = (const float*)d_in[18];
    float* out = (float*)d_out;

    static cudaStream_t s1 = 0;
    static cudaEvent_t e0 = 0, e1 = 0;
    if (!s1) {
        cudaStreamCreateWithFlags(&s1, cudaStreamNonBlocking);
        cudaEventCreateWithFlags(&e0, cudaEventDisableTiming);
        cudaEventCreateWithFlags(&e1, cudaEventDisableTiming);
    }

    const int UPD_BLOCKS = (NCAT * NT / 4 + 32 * NT / 4) / 256;

    cudaEventRecord(e0, 0);

    k_N2<<<64, 256>>>(0, freq, cfreq, amp_re, amp_im, rp, bias, z,
                      memory, fmem, tmem, ts, t_p, ds_p, fmean, x);

    cudaStreamWaitEvent(s1, e0, 0);
    k_misc<<<2, 512, 0, s1>>>(bias, fmean, z, x, ds_p, out);
    k_bigcopy<<<444, 256, 0, s1>>>(memory, fmem, tmem, z, x, t_p, ds_p, out);
    cudaEventRecord(e1, s1);

    // ---- rest of the chain: PDL edges ----
    pdl(k_N3, dim3(448), dim3(512), 0, (const float*)rp,
        (const float*)amp_re, (const float*)amp_im);
    pdl(k_update, dim3(UPD_BLOCKS), dim3(256), 0,
        (const float*)rpg, (const float*)rp, (const float*)agre, (const float*)amp_re,
        (const float*)agim, (const float*)amp_im, (const float*)fg, (const float*)freq, out);
    pdl(k_N2, dim3(64), dim3(256), 1,
        (const float*)(out + OUT_FREQ), (const float*)cfreq,
        (const float*)(out + OUT_ARE), (const float*)(out + OUT_AIM),
        (const float*)(out + OUT_RP), (const float*)bias, (const float*)z,
        (const float*)memory, (const float*)fmem, (const int*)tmem, (const int*)ts,
        (const int*)t_p, (const int*)ds_p, (const float*)fmean, (const float*)x);
    pdl(k_N3, dim3(448), dim3(512), 1, (const float*)(out + OUT_RP),
        (const float*)(out + OUT_ARE), (const float*)(out + OUT_AIM));
    pdl(k_update, dim3(UPD_BLOCKS), dim3(256), 1,
        (const float*)(out + OUT_RPG), (const float*)(out + OUT_RP),
        (const float*)(out + OUT_AGRE), (const float*)(out + OUT_ARE),
        (const float*)(out + OUT_AGIM), (const float*)(out + OUT_AIM),
        (const float*)(out + OUT_FG), (const float*)(out + OUT_FREQ), out);

    // ---- join ----
    cudaStreamWaitEvent(0, e1, 0);
    (void)in_sizes; (void)n_in; (void)out_size;
}